// round 1
// baseline (speedup 1.0000x reference)
#include <cuda_runtime.h>

// LinearAttention_MLP collapses algebraically:
//   k-softmax over n=1 axis == 1; sum_d softmax(q)_d * SCALE == SCALE
//   => attention out = SCALE * v = SCALE * (x @ w_v^T)
//   => final = rmsnorm( x @ (SCALE * w_out @ w_v)^T + b_out ) * g * sqrt(DIM)
// where w_v = rows [1024,1536) of w_qkv.

constexpr int DIM    = 1024;
constexpr int HIDDEN = 512;
constexpr int BATCH  = 16384;

// Scratch for the composed weight matrix W[n][k] (4 MB, static device array).
__device__ float g_W[DIM * DIM];

// ---------------------------------------------------------------------------
// Kernel 1: W[n][k] = 0.125 * sum_c w_out[n][c] * w_qkv[(2*HIDDEN + c)][k]
// GEMM NN: C(1024x1024) = A(1024x512) * B(512x1024). 64x64 tile, BK=16.
// ---------------------------------------------------------------------------
__global__ __launch_bounds__(256) void prep_w_kernel(
    const float* __restrict__ w_qkv, const float* __restrict__ w_out)
{
    __shared__ float As[16][64];  // As[c][n]
    __shared__ float Bs[16][64];  // Bs[c][k]
    const int tid = threadIdx.x;
    const int tx = tid % 16, ty = tid / 16;
    const int n0 = blockIdx.y * 64;
    const int k0 = blockIdx.x * 64;
    const float* __restrict__ B = w_qkv + 2 * HIDDEN * DIM;  // v block rows

    float acc[4][4] = {};

    for (int c0 = 0; c0 < HIDDEN; c0 += 16) {
        // A tile: 64 rows x 16 cols, 1024 floats, 256 threads -> 1 float4 each
        {
            int r  = tid / 4;          // 0..63 (row within tile)
            int cc = (tid % 4) * 4;    // 0,4,8,12
            float4 v = *reinterpret_cast<const float4*>(
                &w_out[(size_t)(n0 + r) * HIDDEN + c0 + cc]);
            As[cc + 0][r] = v.x; As[cc + 1][r] = v.y;
            As[cc + 2][r] = v.z; As[cc + 3][r] = v.w;
        }
        // B tile: 16 rows x 64 cols
        {
            int r  = tid / 16;         // 0..15
            int cc = (tid % 16) * 4;   // 0..60
            float4 v = *reinterpret_cast<const float4*>(
                &B[(size_t)(c0 + r) * DIM + k0 + cc]);
            *reinterpret_cast<float4*>(&Bs[r][cc]) = v;
        }
        __syncthreads();

        #pragma unroll
        for (int c = 0; c < 16; c++) {
            float a[4], b[4];
            #pragma unroll
            for (int i = 0; i < 4; i++) a[i] = As[c][ty * 4 + i];
            #pragma unroll
            for (int j = 0; j < 4; j++) b[j] = Bs[c][tx * 4 + j];
            #pragma unroll
            for (int i = 0; i < 4; i++)
                #pragma unroll
                for (int j = 0; j < 4; j++)
                    acc[i][j] += a[i] * b[j];
        }
        __syncthreads();
    }

    #pragma unroll
    for (int i = 0; i < 4; i++)
        #pragma unroll
        for (int j = 0; j < 4; j++)
            g_W[(size_t)(n0 + ty * 4 + i) * DIM + (k0 + tx * 4 + j)] =
                0.125f * acc[i][j];
}

// ---------------------------------------------------------------------------
// Kernel 2: y[m][n] = sum_k x[m][k] * W[n][k] + b_out[n]
// NT GEMM (both K-major). 128x128 tile, BK=8, 256 threads, 8x8 per thread.
// ---------------------------------------------------------------------------
__global__ __launch_bounds__(256) void gemm_xWT_kernel(
    const float* __restrict__ x, const float* __restrict__ b_out,
    float* __restrict__ y)
{
    __shared__ float As[8][128];  // As[k][m]
    __shared__ float Bs[8][128];  // Bs[k][n]
    const int tid = threadIdx.x;
    const int tx = tid % 16, ty = tid / 16;
    const int m0 = blockIdx.y * 128;
    const int n0 = blockIdx.x * 128;

    float acc[8][8] = {};

    for (int k0 = 0; k0 < DIM; k0 += 8) {
        {
            int r  = tid / 2;          // 0..127
            int cc = (tid % 2) * 4;    // 0 or 4
            float4 va = *reinterpret_cast<const float4*>(
                &x[(size_t)(m0 + r) * DIM + k0 + cc]);
            As[cc + 0][r] = va.x; As[cc + 1][r] = va.y;
            As[cc + 2][r] = va.z; As[cc + 3][r] = va.w;
            float4 vb = *reinterpret_cast<const float4*>(
                &g_W[(size_t)(n0 + r) * DIM + k0 + cc]);
            Bs[cc + 0][r] = vb.x; Bs[cc + 1][r] = vb.y;
            Bs[cc + 2][r] = vb.z; Bs[cc + 3][r] = vb.w;
        }
        __syncthreads();

        #pragma unroll
        for (int k = 0; k < 8; k++) {
            float a[8], b[8];
            #pragma unroll
            for (int i = 0; i < 8; i += 4)
                *reinterpret_cast<float4*>(&a[i]) =
                    *reinterpret_cast<const float4*>(&As[k][ty * 8 + i]);
            #pragma unroll
            for (int j = 0; j < 8; j += 4)
                *reinterpret_cast<float4*>(&b[j]) =
                    *reinterpret_cast<const float4*>(&Bs[k][tx * 8 + j]);
            #pragma unroll
            for (int i = 0; i < 8; i++)
                #pragma unroll
                for (int j = 0; j < 8; j++)
                    acc[i][j] += a[i] * b[j];
        }
        __syncthreads();
    }

    #pragma unroll
    for (int i = 0; i < 8; i++) {
        int m = m0 + ty * 8 + i;
        #pragma unroll
        for (int j = 0; j < 8; j += 4) {
            int n = n0 + tx * 8 + j;
            float4 bv = *reinterpret_cast<const float4*>(&b_out[n]);
            float4 o;
            o.x = acc[i][j + 0] + bv.x;
            o.y = acc[i][j + 1] + bv.y;
            o.z = acc[i][j + 2] + bv.z;
            o.w = acc[i][j + 3] + bv.w;
            *reinterpret_cast<float4*>(&y[(size_t)m * DIM + n]) = o;
        }
    }
}

// ---------------------------------------------------------------------------
// Kernel 3: per-row L2 normalize in place: out = y * (32 / max(||y||, eps)) * g
// One warp per row; 8 float4 per lane.
// ---------------------------------------------------------------------------
__global__ __launch_bounds__(256) void rmsnorm_kernel(
    const float* __restrict__ g, float* __restrict__ y)
{
    const int warp = (blockIdx.x * blockDim.x + threadIdx.x) >> 5;
    const int lane = threadIdx.x & 31;
    if (warp >= BATCH) return;
    float* __restrict__ row = y + (size_t)warp * DIM;

    float4 vals[8];
    float ss = 0.f;
    #pragma unroll
    for (int i = 0; i < 8; i++) {
        vals[i] = *reinterpret_cast<const float4*>(&row[lane * 4 + i * 128]);
        ss += vals[i].x * vals[i].x + vals[i].y * vals[i].y +
              vals[i].z * vals[i].z + vals[i].w * vals[i].w;
    }
    #pragma unroll
    for (int o = 16; o > 0; o >>= 1) ss += __shfl_xor_sync(0xFFFFFFFFu, ss, o);

    const float inv = 32.0f / fmaxf(sqrtf(ss), 1e-12f);

    #pragma unroll
    for (int i = 0; i < 8; i++) {
        int n = lane * 4 + i * 128;
        float4 gv = *reinterpret_cast<const float4*>(&g[n]);
        float4 o;
        o.x = vals[i].x * inv * gv.x;
        o.y = vals[i].y * inv * gv.y;
        o.z = vals[i].z * inv * gv.z;
        o.w = vals[i].w * inv * gv.w;
        *reinterpret_cast<float4*>(&row[n]) = o;
    }
}

// ---------------------------------------------------------------------------
extern "C" void kernel_launch(void* const* d_in, const int* in_sizes, int n_in,
                              void* d_out, int out_size)
{
    const float* x     = (const float*)d_in[0];   // (16384, 1024)
    const float* w_qkv = (const float*)d_in[1];   // (1536, 1024)
    const float* w_out = (const float*)d_in[2];   // (1024, 512)
    const float* b_out = (const float*)d_in[3];   // (1024,)
    const float* g     = (const float*)d_in[4];   // (1, 1024)
    float* out = (float*)d_out;                   // (16384, 1024)

    prep_w_kernel<<<dim3(DIM / 64, DIM / 64), 256>>>(w_qkv, w_out);
    gemm_xWT_kernel<<<dim3(DIM / 128, BATCH / 128), 256>>>(x, b_out, out);
    rmsnorm_kernel<<<(BATCH * 32) / 256, 256>>>(g, out);
}

// round 5
// speedup vs baseline: 2.5171x; 2.5171x over previous
#include <cuda_runtime.h>
#include <cuda_bf16.h>
#include <cstdint>

// Algebraic collapse (validated R1, rel_err 9e-7 fp32):
//   final = rmsnorm( x @ (0.125 * w_out @ w_v)^T + b_out ) * g * 32
// Main GEMM on mma.sync bf16 (HMMA) with 3-pass hi/lo operand split.
// (tcgen05 rejected: harness ptxas targets plain sm_103, no 'a' features.)

constexpr int DIM    = 1024;
constexpr int HIDDEN = 512;
constexpr int BATCH  = 16384;

constexpr int BM = 128;   // batch rows per CTA (GEMM M)
constexpr int BN = 128;   // dim cols per CTA (GEMM N)
constexpr int BK = 64;    // k per chunk
constexpr int KCHUNKS = DIM / BK;  // 16

constexpr uint32_t PITCH = 144;                 // 128B data + 16B pad per row
constexpr uint32_t SA_HI = 0;
constexpr uint32_t SA_LO = 128 * PITCH;         // 18432
constexpr uint32_t SB_HI = 2 * 128 * PITCH;     // 36864
constexpr uint32_t SB_LO = 3 * 128 * PITCH;     // 55296
constexpr uint32_t STAGE = 4 * 128 * PITCH;     // 73728
constexpr uint32_t GEMM_SMEM = 2 * STAGE;       // 147456

// Static device scratch (allocation-free rule).
__device__ __nv_bfloat16 g_Xhi[BATCH * DIM];
__device__ __nv_bfloat16 g_Xlo[BATCH * DIM];
__device__ __nv_bfloat16 g_Whi[DIM * DIM];
__device__ __nv_bfloat16 g_Wlo[DIM * DIM];

// ---------------------------------------------------------------------------
// PTX helpers (all sm_80-era, safe for plain sm_103 target)
// ---------------------------------------------------------------------------
__device__ __forceinline__ uint32_t smem_u32(const void* p) {
    uint32_t a;
    asm("{ .reg .u64 t; cvta.to.shared.u64 t, %1; cvt.u32.u64 %0, t; }"
        : "=r"(a) : "l"(p));
    return a;
}
__device__ __forceinline__ void cp16(uint32_t dst, const void* src) {
    asm volatile("cp.async.cg.shared.global [%0], [%1], 16;"
                 :: "r"(dst), "l"(src) : "memory");
}
#define CP_COMMIT() asm volatile("cp.async.commit_group;" ::: "memory")
#define CP_WAIT(n)  asm volatile("cp.async.wait_group %0;" :: "n"(n) : "memory")

#define LDSM4(r, addr)                                                         \
    asm volatile("ldmatrix.sync.aligned.m8n8.x4.shared.b16 "                   \
                 "{%0, %1, %2, %3}, [%4];"                                     \
                 : "=r"((r)[0]), "=r"((r)[1]), "=r"((r)[2]), "=r"((r)[3])      \
                 : "r"(addr))

#define MMA16816(c, a, b)                                                      \
    asm volatile("mma.sync.aligned.m16n8k16.row.col.f32.bf16.bf16.f32 "        \
                 "{%0, %1, %2, %3}, {%4, %5, %6, %7}, {%8, %9}, "              \
                 "{%0, %1, %2, %3};"                                           \
                 : "+f"((c)[0]), "+f"((c)[1]), "+f"((c)[2]), "+f"((c)[3])      \
                 : "r"((a)[0]), "r"((a)[1]), "r"((a)[2]), "r"((a)[3]),         \
                   "r"((b)[0]), "r"((b)[1]))

// ---------------------------------------------------------------------------
// Split x into bf16 hi/lo
// ---------------------------------------------------------------------------
__global__ __launch_bounds__(256) void conv_x_kernel(const float4* __restrict__ x4)
{
    int i = blockIdx.x * blockDim.x + threadIdx.x;  // per float4
    float4 v = x4[i];
    __nv_bfloat16 h0 = __float2bfloat16(v.x), h1 = __float2bfloat16(v.y);
    __nv_bfloat16 h2 = __float2bfloat16(v.z), h3 = __float2bfloat16(v.w);
    __nv_bfloat162* hi = reinterpret_cast<__nv_bfloat162*>(g_Xhi);
    __nv_bfloat162* lo = reinterpret_cast<__nv_bfloat162*>(g_Xlo);
    hi[i * 2 + 0] = __nv_bfloat162(h0, h1);
    hi[i * 2 + 1] = __nv_bfloat162(h2, h3);
    lo[i * 2 + 0] = __nv_bfloat162(__float2bfloat16(v.x - __bfloat162float(h0)),
                                   __float2bfloat16(v.y - __bfloat162float(h1)));
    lo[i * 2 + 1] = __nv_bfloat162(__float2bfloat16(v.z - __bfloat162float(h2)),
                                   __float2bfloat16(v.w - __bfloat162float(h3)));
}

// ---------------------------------------------------------------------------
// W = 0.125 * w_out @ w_v  (fp32 SIMT; 44us, near fp32 floor), bf16 hi/lo out
// ---------------------------------------------------------------------------
__global__ __launch_bounds__(256) void prep_w_kernel(
    const float* __restrict__ w_qkv, const float* __restrict__ w_out)
{
    __shared__ float As[16][64];
    __shared__ float Bs[16][64];
    const int tid = threadIdx.x;
    const int tx = tid % 16, ty = tid / 16;
    const int n0 = blockIdx.y * 64;
    const int k0 = blockIdx.x * 64;
    const float* __restrict__ B = w_qkv + 2 * HIDDEN * DIM;

    float acc[4][4] = {};
    for (int c0 = 0; c0 < HIDDEN; c0 += 16) {
        {
            int r = tid / 4, cc = (tid % 4) * 4;
            float4 v = *reinterpret_cast<const float4*>(
                &w_out[(size_t)(n0 + r) * HIDDEN + c0 + cc]);
            As[cc + 0][r] = v.x; As[cc + 1][r] = v.y;
            As[cc + 2][r] = v.z; As[cc + 3][r] = v.w;
        }
        {
            int r = tid / 16, cc = (tid % 16) * 4;
            float4 v = *reinterpret_cast<const float4*>(
                &B[(size_t)(c0 + r) * DIM + k0 + cc]);
            *reinterpret_cast<float4*>(&Bs[r][cc]) = v;
        }
        __syncthreads();
        #pragma unroll
        for (int c = 0; c < 16; c++) {
            float a[4], b[4];
            #pragma unroll
            for (int i = 0; i < 4; i++) a[i] = As[c][ty * 4 + i];
            #pragma unroll
            for (int j = 0; j < 4; j++) b[j] = Bs[c][tx * 4 + j];
            #pragma unroll
            for (int i = 0; i < 4; i++)
                #pragma unroll
                for (int j = 0; j < 4; j++)
                    acc[i][j] += a[i] * b[j];
        }
        __syncthreads();
    }
    #pragma unroll
    for (int i = 0; i < 4; i++)
        #pragma unroll
        for (int j = 0; j < 4; j++) {
            float w = 0.125f * acc[i][j];
            size_t idx = (size_t)(n0 + ty * 4 + i) * DIM + (k0 + tx * 4 + j);
            __nv_bfloat16 h = __float2bfloat16(w);
            g_Whi[idx] = h;
            g_Wlo[idx] = __float2bfloat16(w - __bfloat162float(h));
        }
}

// ---------------------------------------------------------------------------
// Main GEMM: out[b][n] = sum_k X[b][k] * W[n][k] + b_out[n]
// mma.sync m16n8k16 bf16, 3-pass split, cp.async double buffer.
// ---------------------------------------------------------------------------
__device__ __forceinline__ void load_stage(uint32_t sb, int s, int m0b, int n0b,
                                           int kc, int tid)
{
    const uint32_t st = sb + (uint32_t)s * STAGE;
    const char* xh = reinterpret_cast<const char*>(g_Xhi);
    const char* xl = reinterpret_cast<const char*>(g_Xlo);
    const char* wh = reinterpret_cast<const char*>(g_Whi);
    const char* wl = reinterpret_cast<const char*>(g_Wlo);
    const size_t kb = (size_t)kc * 128;  // BK*2 bytes

    #pragma unroll
    for (int j = 0; j < 4; j++) {
        int i = tid + j * 256;
        int r = i >> 3, c = i & 7;
        uint32_t so = (uint32_t)r * PITCH + c * 16;
        size_t ga = (size_t)(m0b + r) * 2048 + kb + c * 16;
        size_t gb = (size_t)(n0b + r) * 2048 + kb + c * 16;
        cp16(st + SA_HI + so, xh + ga);
        cp16(st + SA_LO + so, xl + ga);
        cp16(st + SB_HI + so, wh + gb);
        cp16(st + SB_LO + so, wl + gb);
    }
}

__global__ __launch_bounds__(256) void gemm_mma_kernel(
    const float* __restrict__ b_out, float* __restrict__ out)
{
    extern __shared__ char smem[];
    const uint32_t sb = smem_u32(smem);
    const int tid = threadIdx.x;
    const int lane = tid & 31, wid = tid >> 5;
    const int wm = wid & 1, wn = wid >> 1;        // 2 x 4 warp grid
    const int m0b = blockIdx.y * BM;
    const int n0b = blockIdx.x * BN;

    float c[4][4][4] = {};                        // [mi][ni][reg]

    // per-lane ldmatrix base offsets
    const int rowA = lane & 15;
    const int colA = (lane >> 4) * 8;
    const int rowB = (lane & 7) + ((lane >> 4) << 3);
    const int colB = ((lane >> 3) & 1) * 8;
    const uint32_t pA = (uint32_t)(wm * 64 + rowA) * PITCH + colA * 2;
    const uint32_t pB = (uint32_t)(wn * 32 + rowB) * PITCH + colB * 2;

    load_stage(sb, 0, m0b, n0b, 0, tid);
    CP_COMMIT();

    for (int kc = 0; kc < KCHUNKS; kc++) {
        const int s = kc & 1;
        if (kc + 1 < KCHUNKS) {
            load_stage(sb, s ^ 1, m0b, n0b, kc + 1, tid);
            CP_COMMIT();
            CP_WAIT(1);
        } else {
            CP_WAIT(0);
        }
        __syncthreads();

        const uint32_t st = sb + (uint32_t)s * STAGE;
        #pragma unroll
        for (int ks = 0; ks < 4; ks++) {
            uint32_t ah[4][4], al[4][4];
            #pragma unroll
            for (int mi = 0; mi < 4; mi++) {
                uint32_t adr = st + SA_HI + pA + mi * (16 * PITCH) + ks * 32;
                LDSM4(ah[mi], adr);
                LDSM4(al[mi], adr + (SA_LO - SA_HI));
            }
            uint32_t bh[4][2], bl[4][2];
            #pragma unroll
            for (int np = 0; np < 2; np++) {
                uint32_t adr = st + SB_HI + pB + np * (16 * PITCH) + ks * 32;
                uint32_t r[4];
                LDSM4(r, adr);
                bh[np * 2][0] = r[0]; bh[np * 2][1] = r[1];
                bh[np * 2 + 1][0] = r[2]; bh[np * 2 + 1][1] = r[3];
                LDSM4(r, adr + (SB_LO - SB_HI));
                bl[np * 2][0] = r[0]; bl[np * 2][1] = r[1];
                bl[np * 2 + 1][0] = r[2]; bl[np * 2 + 1][1] = r[3];
            }
            #pragma unroll
            for (int mi = 0; mi < 4; mi++)
                #pragma unroll
                for (int ni = 0; ni < 4; ni++) {
                    MMA16816(c[mi][ni], ah[mi], bh[ni]);
                    MMA16816(c[mi][ni], ah[mi], bl[ni]);
                    MMA16816(c[mi][ni], al[mi], bh[ni]);
                }
        }
        __syncthreads();
    }

    // epilogue: + bias, fp32 store
    const int mbase = m0b + wm * 64 + (lane >> 2);
    const int nbase = n0b + wn * 32 + (lane & 3) * 2;
    #pragma unroll
    for (int ni = 0; ni < 4; ni++) {
        const int n = nbase + ni * 8;
        const float2 bias = *reinterpret_cast<const float2*>(&b_out[n]);
        #pragma unroll
        for (int mi = 0; mi < 4; mi++) {
            const int m = mbase + mi * 16;
            float2 v0 = { c[mi][ni][0] + bias.x, c[mi][ni][1] + bias.y };
            float2 v1 = { c[mi][ni][2] + bias.x, c[mi][ni][3] + bias.y };
            *reinterpret_cast<float2*>(&out[(size_t)m * DIM + n]) = v0;
            *reinterpret_cast<float2*>(&out[(size_t)(m + 8) * DIM + n]) = v1;
        }
    }
}

// ---------------------------------------------------------------------------
// Row L2-normalize: out = y * (32/max(||y||,eps)) * g
// ---------------------------------------------------------------------------
__global__ __launch_bounds__(256) void rmsnorm_kernel(
    const float* __restrict__ g, float* __restrict__ y)
{
    const int warp = (blockIdx.x * blockDim.x + threadIdx.x) >> 5;
    const int lane = threadIdx.x & 31;
    if (warp >= BATCH) return;
    float* __restrict__ row = y + (size_t)warp * DIM;

    float4 vals[8];
    float ss = 0.f;
    #pragma unroll
    for (int i = 0; i < 8; i++) {
        vals[i] = *reinterpret_cast<const float4*>(&row[lane * 4 + i * 128]);
        ss += vals[i].x * vals[i].x + vals[i].y * vals[i].y +
              vals[i].z * vals[i].z + vals[i].w * vals[i].w;
    }
    #pragma unroll
    for (int o = 16; o > 0; o >>= 1) ss += __shfl_xor_sync(0xFFFFFFFFu, ss, o);
    const float inv = 32.0f / fmaxf(sqrtf(ss), 1e-12f);
    #pragma unroll
    for (int i = 0; i < 8; i++) {
        int n = lane * 4 + i * 128;
        float4 gv = *reinterpret_cast<const float4*>(&g[n]);
        float4 o;
        o.x = vals[i].x * inv * gv.x;
        o.y = vals[i].y * inv * gv.y;
        o.z = vals[i].z * inv * gv.z;
        o.w = vals[i].w * inv * gv.w;
        *reinterpret_cast<float4*>(&row[n]) = o;
    }
}

// ---------------------------------------------------------------------------
extern "C" void kernel_launch(void* const* d_in, const int* in_sizes, int n_in,
                              void* d_out, int out_size)
{
    const float* x     = (const float*)d_in[0];
    const float* w_qkv = (const float*)d_in[1];
    const float* w_out = (const float*)d_in[2];
    const float* b_out = (const float*)d_in[3];
    const float* g     = (const float*)d_in[4];
    float* out = (float*)d_out;

    cudaFuncSetAttribute(gemm_mma_kernel,
                         cudaFuncAttributeMaxDynamicSharedMemorySize, GEMM_SMEM);

    conv_x_kernel<<<(BATCH * DIM / 4) / 256, 256>>>((const float4*)x);
    prep_w_kernel<<<dim3(DIM / 64, DIM / 64), 256>>>(w_qkv, w_out);
    gemm_mma_kernel<<<dim3(DIM / BN, BATCH / BM), 256, GEMM_SMEM>>>(b_out, out);
    rmsnorm_kernel<<<(BATCH * 32) / 256, 256>>>(g, out);
}

// round 6
// speedup vs baseline: 5.3781x; 2.1366x over previous
#include <cuda_runtime.h>
#include <cuda_fp16.h>
#include <cstdint>

// Algebraic collapse (validated R1/R5):
//   final = rmsnorm( x @ (0.125 * w_out @ w_v)^T + b_out ) * g * 32
// This round: single-pass fp16 HMMA GEMM (norm-based rel_err model ~3e-4,
// gate 1e-3). W stored unscaled in fp16; 0.125 folded into epilogue.

constexpr int DIM    = 1024;
constexpr int HIDDEN = 512;
constexpr int BATCH  = 16384;

constexpr int BM = 128;   // batch rows per CTA (GEMM M)
constexpr int BN = 128;   // dim cols per CTA (GEMM N)
constexpr int BK = 64;    // k per chunk
constexpr int KCHUNKS = DIM / BK;  // 16
constexpr int NSTAGE = 3;

constexpr uint32_t PITCH = 144;                 // 128B data + 16B pad per row
constexpr uint32_t SA = 0;                      // x tile: 128 rows
constexpr uint32_t SB = 128 * PITCH;            // W tile: 128 rows
constexpr uint32_t STAGE = 2 * 128 * PITCH;     // 36864
constexpr uint32_t GEMM_SMEM = NSTAGE * STAGE;  // 110592

// Static device scratch (allocation-free rule).
__device__ __half g_Xh[BATCH * DIM];
__device__ __half g_Wh[DIM * DIM];              // unscaled w_out @ w_v

// ---------------------------------------------------------------------------
// PTX helpers (sm_80-era only; harness ptxas targets plain sm_103)
// ---------------------------------------------------------------------------
__device__ __forceinline__ uint32_t smem_u32(const void* p) {
    uint32_t a;
    asm("{ .reg .u64 t; cvta.to.shared.u64 t, %1; cvt.u32.u64 %0, t; }"
        : "=r"(a) : "l"(p));
    return a;
}
__device__ __forceinline__ void cp16(uint32_t dst, const void* src) {
    asm volatile("cp.async.cg.shared.global [%0], [%1], 16;"
                 :: "r"(dst), "l"(src) : "memory");
}
#define CP_COMMIT() asm volatile("cp.async.commit_group;" ::: "memory")
#define CP_WAIT(n)  asm volatile("cp.async.wait_group %0;" :: "n"(n) : "memory")

#define LDSM4(r, addr)                                                         \
    asm volatile("ldmatrix.sync.aligned.m8n8.x4.shared.b16 "                   \
                 "{%0, %1, %2, %3}, [%4];"                                     \
                 : "=r"((r)[0]), "=r"((r)[1]), "=r"((r)[2]), "=r"((r)[3])      \
                 : "r"(addr))

#define MMA16816(c, a, b)                                                      \
    asm volatile("mma.sync.aligned.m16n8k16.row.col.f32.f16.f16.f32 "          \
                 "{%0, %1, %2, %3}, {%4, %5, %6, %7}, {%8, %9}, "              \
                 "{%0, %1, %2, %3};"                                           \
                 : "+f"((c)[0]), "+f"((c)[1]), "+f"((c)[2]), "+f"((c)[3])      \
                 : "r"((a)[0]), "r"((a)[1]), "r"((a)[2]), "r"((a)[3]),         \
                   "r"((b)[0]), "r"((b)[1]))

// ---------------------------------------------------------------------------
// Fused prep kernel: blocks [0,256) compute W = w_out @ w_v  (fp32 SIMT,
// fp16 out, unscaled); blocks [256,512) convert x -> fp16 grid-stride.
// ---------------------------------------------------------------------------
__global__ __launch_bounds__(256) void prep_fused_kernel(
    const float4* __restrict__ x4,
    const float* __restrict__ w_qkv, const float* __restrict__ w_out)
{
    const int tid = threadIdx.x;

    if (blockIdx.x >= 256) {
        // ---- conv part: 256 blocks, grid-stride over 4,194,304 float4 ----
        const int b2 = blockIdx.x - 256;
        __half2* __restrict__ xo = reinterpret_cast<__half2*>(g_Xh);
        int i = b2 * 256 + tid;
        #pragma unroll 4
        for (int it = 0; it < (BATCH * DIM / 4) / 65536; it++, i += 65536) {
            float4 v = x4[i];
            xo[i * 2 + 0] = __floats2half2_rn(v.x, v.y);
            xo[i * 2 + 1] = __floats2half2_rn(v.z, v.w);
        }
        return;
    }

    // ---- prep_w part: 256 blocks (16 x 16 tiles of 64x64) ----
    __shared__ float As[16][64];
    __shared__ float Bs[16][64];
    const int tx = tid % 16, ty = tid / 16;
    const int n0 = (blockIdx.x / 16) * 64;
    const int k0 = (blockIdx.x % 16) * 64;
    const float* __restrict__ B = w_qkv + 2 * HIDDEN * DIM;

    float acc[4][4] = {};
    for (int c0 = 0; c0 < HIDDEN; c0 += 16) {
        {
            int r = tid / 4, cc = (tid % 4) * 4;
            float4 v = *reinterpret_cast<const float4*>(
                &w_out[(size_t)(n0 + r) * HIDDEN + c0 + cc]);
            As[cc + 0][r] = v.x; As[cc + 1][r] = v.y;
            As[cc + 2][r] = v.z; As[cc + 3][r] = v.w;
        }
        {
            int r = tid / 16, cc = (tid % 16) * 4;
            float4 v = *reinterpret_cast<const float4*>(
                &B[(size_t)(c0 + r) * DIM + k0 + cc]);
            *reinterpret_cast<float4*>(&Bs[r][cc]) = v;
        }
        __syncthreads();
        #pragma unroll
        for (int c = 0; c < 16; c++) {
            float a[4], b[4];
            #pragma unroll
            for (int i = 0; i < 4; i++) a[i] = As[c][ty * 4 + i];
            #pragma unroll
            for (int j = 0; j < 4; j++) b[j] = Bs[c][tx * 4 + j];
            #pragma unroll
            for (int i = 0; i < 4; i++)
                #pragma unroll
                for (int j = 0; j < 4; j++)
                    acc[i][j] += a[i] * b[j];
        }
        __syncthreads();
    }
    #pragma unroll
    for (int i = 0; i < 4; i++)
        #pragma unroll
        for (int j = 0; j < 2; j++)
            *reinterpret_cast<__half2*>(
                &g_Wh[(size_t)(n0 + ty * 4 + i) * DIM + k0 + tx * 4 + j * 2]) =
                __floats2half2_rn(acc[i][j * 2], acc[i][j * 2 + 1]);
}

// ---------------------------------------------------------------------------
// Main GEMM: out[b][n] = 0.125 * sum_k X[b][k] * W[n][k] + b_out[n]
// fp16 m16n8k16 mma, 3-stage cp.async pipeline, 2 CTAs/SM.
// ---------------------------------------------------------------------------
__device__ __forceinline__ void load_stage(uint32_t sb, int s, int m0b, int n0b,
                                           int kc, int tid)
{
    const uint32_t st = sb + (uint32_t)s * STAGE;
    const char* xh = reinterpret_cast<const char*>(g_Xh);
    const char* wh = reinterpret_cast<const char*>(g_Wh);
    const size_t kb = (size_t)kc * 128;  // BK*2 bytes

    #pragma unroll
    for (int j = 0; j < 4; j++) {
        int i = tid + j * 256;           // [0,1024): 128 rows x 8 cols
        int r = i >> 3, c = i & 7;
        uint32_t so = (uint32_t)r * PITCH + c * 16;
        cp16(st + SA + so, xh + (size_t)(m0b + r) * 2048 + kb + c * 16);
        cp16(st + SB + so, wh + (size_t)(n0b + r) * 2048 + kb + c * 16);
    }
}

__global__ __launch_bounds__(256, 2) void gemm_mma_kernel(
    const float* __restrict__ b_out, float* __restrict__ out)
{
    extern __shared__ char smem[];
    const uint32_t sb = smem_u32(smem);
    const int tid = threadIdx.x;
    const int lane = tid & 31, wid = tid >> 5;
    const int wm = wid & 1, wn = wid >> 1;        // 2 x 4 warp grid
    const int m0b = blockIdx.y * BM;
    const int n0b = blockIdx.x * BN;

    float c[4][4][4] = {};                        // [mi][ni][reg]

    // per-lane ldmatrix base offsets (layout validated in R5)
    const int rowA = lane & 15;
    const int colA = (lane >> 4) * 8;
    const int rowB = (lane & 7) + ((lane >> 4) << 3);
    const int colB = ((lane >> 3) & 1) * 8;
    const uint32_t pA = (uint32_t)(wm * 64 + rowA) * PITCH + colA * 2;
    const uint32_t pB = (uint32_t)(wn * 32 + rowB) * PITCH + colB * 2;

    load_stage(sb, 0, m0b, n0b, 0, tid);
    CP_COMMIT();
    load_stage(sb, 1, m0b, n0b, 1, tid);
    CP_COMMIT();

    int sc = 0;                                   // stage of chunk kc
    for (int kc = 0; kc < KCHUNKS; kc++) {
        CP_WAIT(1);
        __syncthreads();

        // prefetch kc+2 into the stage freed at kc-1
        if (kc + 2 < KCHUNKS) {
            int sp = sc + 2; if (sp >= NSTAGE) sp -= NSTAGE;
            load_stage(sb, sp, m0b, n0b, kc + 2, tid);
        }
        CP_COMMIT();

        const uint32_t st = sb + (uint32_t)sc * STAGE;
        #pragma unroll
        for (int ks = 0; ks < 4; ks++) {
            uint32_t a[4][4];
            #pragma unroll
            for (int mi = 0; mi < 4; mi++)
                LDSM4(a[mi], st + SA + pA + mi * (16 * PITCH) + ks * 32);
            uint32_t b[4][2];
            #pragma unroll
            for (int np = 0; np < 2; np++) {
                uint32_t r[4];
                LDSM4(r, st + SB + pB + np * (16 * PITCH) + ks * 32);
                b[np * 2][0] = r[0]; b[np * 2][1] = r[1];
                b[np * 2 + 1][0] = r[2]; b[np * 2 + 1][1] = r[3];
            }
            #pragma unroll
            for (int mi = 0; mi < 4; mi++)
                #pragma unroll
                for (int ni = 0; ni < 4; ni++)
                    MMA16816(c[mi][ni], a[mi], b[ni]);
        }
        __syncthreads();
        if (++sc >= NSTAGE) sc -= NSTAGE;
    }

    // epilogue: * 0.125 + bias, fp32 store
    const int mbase = m0b + wm * 64 + (lane >> 2);
    const int nbase = n0b + wn * 32 + (lane & 3) * 2;
    #pragma unroll
    for (int ni = 0; ni < 4; ni++) {
        const int n = nbase + ni * 8;
        const float2 bias = *reinterpret_cast<const float2*>(&b_out[n]);
        #pragma unroll
        for (int mi = 0; mi < 4; mi++) {
            const int m = mbase + mi * 16;
            float2 v0 = { fmaf(0.125f, c[mi][ni][0], bias.x),
                          fmaf(0.125f, c[mi][ni][1], bias.y) };
            float2 v1 = { fmaf(0.125f, c[mi][ni][2], bias.x),
                          fmaf(0.125f, c[mi][ni][3], bias.y) };
            *reinterpret_cast<float2*>(&out[(size_t)m * DIM + n]) = v0;
            *reinterpret_cast<float2*>(&out[(size_t)(m + 8) * DIM + n]) = v1;
        }
    }
}

// ---------------------------------------------------------------------------
// Row L2-normalize: out = y * (32/max(||y||,eps)) * g
// ---------------------------------------------------------------------------
__global__ __launch_bounds__(256) void rmsnorm_kernel(
    const float* __restrict__ g, float* __restrict__ y)
{
    const int warp = (blockIdx.x * blockDim.x + threadIdx.x) >> 5;
    const int lane = threadIdx.x & 31;
    if (warp >= BATCH) return;
    float* __restrict__ row = y + (size_t)warp * DIM;

    float4 vals[8];
    float ss = 0.f;
    #pragma unroll
    for (int i = 0; i < 8; i++) {
        vals[i] = *reinterpret_cast<const float4*>(&row[lane * 4 + i * 128]);
        ss += vals[i].x * vals[i].x + vals[i].y * vals[i].y +
              vals[i].z * vals[i].z + vals[i].w * vals[i].w;
    }
    #pragma unroll
    for (int o = 16; o > 0; o >>= 1) ss += __shfl_xor_sync(0xFFFFFFFFu, ss, o);
    const float inv = 32.0f / fmaxf(sqrtf(ss), 1e-12f);
    #pragma unroll
    for (int i = 0; i < 8; i++) {
        int n = lane * 4 + i * 128;
        float4 gv = *reinterpret_cast<const float4*>(&g[n]);
        float4 o;
        o.x = vals[i].x * inv * gv.x;
        o.y = vals[i].y * inv * gv.y;
        o.z = vals[i].z * inv * gv.z;
        o.w = vals[i].w * inv * gv.w;
        *reinterpret_cast<float4*>(&row[n]) = o;
    }
}

// ---------------------------------------------------------------------------
extern "C" void kernel_launch(void* const* d_in, const int* in_sizes, int n_in,
                              void* d_out, int out_size)
{
    const float* x     = (const float*)d_in[0];
    const float* w_qkv = (const float*)d_in[1];
    const float* w_out = (const float*)d_in[2];
    const float* b_out = (const float*)d_in[3];
    const float* g     = (const float*)d_in[4];
    float* out = (float*)d_out;

    cudaFuncSetAttribute(gemm_mma_kernel,
                         cudaFuncAttributeMaxDynamicSharedMemorySize, GEMM_SMEM);

    prep_fused_kernel<<<512, 256>>>((const float4*)x, w_qkv, w_out);
    gemm_mma_kernel<<<dim3(DIM / BN, BATCH / BM), 256, GEMM_SMEM>>>(b_out, out);
    rmsnorm_kernel<<<(BATCH * 32) / 256, 256>>>(g, out);
}

// round 7
// speedup vs baseline: 6.0393x; 1.1229x over previous
#include <cuda_runtime.h>
#include <cuda_fp16.h>
#include <cstdint>

// final = rmsnorm( x @ (0.125 * w_out @ w_v)^T + b_out ) * g * 32
// R7: conv kernel (pure memory) -> prep GEMM on HMMA (3-pass fp16 split)
//     -> main GEMM single-pass fp16 HMMA -> row L2 norm.

constexpr int DIM    = 1024;
constexpr int HIDDEN = 512;
constexpr int BATCH  = 16384;

constexpr int BM = 128;
constexpr int BN = 128;
constexpr int BK = 64;                          // k per chunk (128B fp16)
constexpr int KCHUNKS  = DIM / BK;              // 16 (main)
constexpr int KCHUNKSP = HIDDEN / BK;           // 8  (prep)
constexpr int NSTAGE = 3;

constexpr uint32_t PITCH = 144;                 // 128B data + 16B pad
constexpr uint32_t SA = 0;
constexpr uint32_t SB = 128 * PITCH;
constexpr uint32_t STAGE = 2 * 128 * PITCH;     // 36864
constexpr uint32_t GEMM_SMEM = NSTAGE * STAGE;  // 110592

// prep-GEMM stage: A_hi, A_lo, B_hi, B_lo (128 rows each)
constexpr uint32_t PA_HI = 0;
constexpr uint32_t PA_LO = 128 * PITCH;
constexpr uint32_t PB_HI = 2 * 128 * PITCH;
constexpr uint32_t PB_LO = 3 * 128 * PITCH;
constexpr uint32_t STAGE_P = 4 * 128 * PITCH;   // 73728
constexpr uint32_t PREP_SMEM = 2 * STAGE_P;     // 147456

// Static device scratch (allocation-free rule).
__device__ __half g_Xh[BATCH * DIM];            // x fp16
__device__ __half g_Wh[DIM * DIM];              // W = w_out @ w_v (unscaled)
__device__ __half g_WOhi[DIM * HIDDEN];         // w_out hi  [n][c]
__device__ __half g_WOlo[DIM * HIDDEN];         // w_out lo
__device__ __half g_WvThi[DIM * HIDDEN];        // w_v^T hi  [k][c]
__device__ __half g_WvTlo[DIM * HIDDEN];        // w_v^T lo

// ---------------------------------------------------------------------------
// PTX helpers (sm_80-era only; harness ptxas targets plain sm_103)
// ---------------------------------------------------------------------------
__device__ __forceinline__ uint32_t smem_u32(const void* p) {
    uint32_t a;
    asm("{ .reg .u64 t; cvta.to.shared.u64 t, %1; cvt.u32.u64 %0, t; }"
        : "=r"(a) : "l"(p));
    return a;
}
__device__ __forceinline__ void cp16(uint32_t dst, const void* src) {
    asm volatile("cp.async.cg.shared.global [%0], [%1], 16;"
                 :: "r"(dst), "l"(src) : "memory");
}
#define CP_COMMIT() asm volatile("cp.async.commit_group;" ::: "memory")
#define CP_WAIT(n)  asm volatile("cp.async.wait_group %0;" :: "n"(n) : "memory")

#define LDSM4(r, addr)                                                         \
    asm volatile("ldmatrix.sync.aligned.m8n8.x4.shared.b16 "                   \
                 "{%0, %1, %2, %3}, [%4];"                                     \
                 : "=r"((r)[0]), "=r"((r)[1]), "=r"((r)[2]), "=r"((r)[3])      \
                 : "r"(addr))

#define MMA16816(c, a, b)                                                      \
    asm volatile("mma.sync.aligned.m16n8k16.row.col.f32.f16.f16.f32 "          \
                 "{%0, %1, %2, %3}, {%4, %5, %6, %7}, {%8, %9}, "              \
                 "{%0, %1, %2, %3};"                                           \
                 : "+f"((c)[0]), "+f"((c)[1]), "+f"((c)[2]), "+f"((c)[3])      \
                 : "r"((a)[0]), "r"((a)[1]), "r"((a)[2]), "r"((a)[3]),         \
                   "r"((b)[0]), "r"((b)[1]))

// ---------------------------------------------------------------------------
// Conversion kernel (pure memory):
//   blocks [0,2048)      : x fp32 -> fp16
//   blocks [2048,2176)   : w_out -> fp16 hi/lo  [n][c]
//   blocks [2176,2688)   : w_v -> transposed fp16 hi/lo  [k][c]
// ---------------------------------------------------------------------------
__global__ __launch_bounds__(256) void conv_kernel(
    const float4* __restrict__ x4,
    const float* __restrict__ w_qkv, const float* __restrict__ w_out)
{
    const int tid = threadIdx.x;
    const int b = blockIdx.x;

    if (b < 2048) {
        // x: 4,194,304 float4 over 2048 blocks x 256 threads x 8 iters
        __half2* __restrict__ xo = reinterpret_cast<__half2*>(g_Xh);
        int i = b * 256 + tid;
        #pragma unroll
        for (int it = 0; it < 8; it++, i += 524288) {
            float4 v = x4[i];
            xo[i * 2 + 0] = __floats2half2_rn(v.x, v.y);
            xo[i * 2 + 1] = __floats2half2_rn(v.z, v.w);
        }
        return;
    }

    if (b < 2176) {
        // w_out: 131072 float4 over 128 blocks x 256 threads x 4 iters
        const float4* __restrict__ w4 = reinterpret_cast<const float4*>(w_out);
        int i = (b - 2048) * 256 + tid;
        #pragma unroll
        for (int it = 0; it < 4; it++, i += 32768) {
            float4 v = w4[i];
            __half h0 = __float2half_rn(v.x), h1 = __float2half_rn(v.y);
            __half h2 = __float2half_rn(v.z), h3 = __float2half_rn(v.w);
            __half2* ho = reinterpret_cast<__half2*>(g_WOhi);
            __half2* lo = reinterpret_cast<__half2*>(g_WOlo);
            ho[i * 2 + 0] = __half2(h0, h1);
            ho[i * 2 + 1] = __half2(h2, h3);
            lo[i * 2 + 0] = __half2(__float2half_rn(v.x - __half2float(h0)),
                                    __float2half_rn(v.y - __half2float(h1)));
            lo[i * 2 + 1] = __half2(__float2half_rn(v.z - __half2float(h2)),
                                    __float2half_rn(v.w - __half2float(h3)));
        }
        return;
    }

    // w_v transpose: w_v[c][k] (rows [1024,1536) of w_qkv) -> WvT[k][c]
    __shared__ float tile[32][33];
    const int bb = b - 2176;                 // 0..511
    const int k0 = (bb & 31) * 32;           // 32 k-tiles
    const int c0 = (bb >> 5) * 32;           // 16 c-tiles
    const int tx = tid & 31, ty = tid >> 5;  // 32 x 8
    const float* __restrict__ wv = w_qkv + (size_t)2 * HIDDEN * DIM;

    #pragma unroll
    for (int j = 0; j < 4; j++)
        tile[ty + j * 8][tx] = wv[(size_t)(c0 + ty + j * 8) * DIM + k0 + tx];
    __syncthreads();
    #pragma unroll
    for (int j = 0; j < 4; j++) {
        int k = k0 + ty + j * 8;
        float v = tile[tx][ty + j * 8];
        __half h = __float2half_rn(v);
        g_WvThi[(size_t)k * HIDDEN + c0 + tx] = h;
        g_WvTlo[(size_t)k * HIDDEN + c0 + tx] =
            __float2half_rn(v - __half2float(h));
    }
}

// ---------------------------------------------------------------------------
// Prep GEMM (HMMA, 3-pass fp16 split): W[n][k] = sum_c w_out[n][c]*w_vT[k][c]
// A rows = n (g_WOhi/lo), B rows = k (g_WvThi/lo), reduction c contiguous.
// ---------------------------------------------------------------------------
__device__ __forceinline__ void load_stage_p(uint32_t sb, int s, int m0b,
                                             int n0b, int kc, int tid)
{
    const uint32_t st = sb + (uint32_t)s * STAGE_P;
    const char* ah = reinterpret_cast<const char*>(g_WOhi);
    const char* al = reinterpret_cast<const char*>(g_WOlo);
    const char* bh = reinterpret_cast<const char*>(g_WvThi);
    const char* bl = reinterpret_cast<const char*>(g_WvTlo);
    const size_t kb = (size_t)kc * 128;  // BK*2 bytes

    #pragma unroll
    for (int j = 0; j < 4; j++) {
        int i = tid + j * 256;
        int r = i >> 3, c = i & 7;
        uint32_t so = (uint32_t)r * PITCH + c * 16;
        size_t ga = (size_t)(m0b + r) * 1024 + kb + c * 16;   // row = 512 fp16
        size_t gb = (size_t)(n0b + r) * 1024 + kb + c * 16;
        cp16(st + PA_HI + so, ah + ga);
        cp16(st + PA_LO + so, al + ga);
        cp16(st + PB_HI + so, bh + gb);
        cp16(st + PB_LO + so, bl + gb);
    }
}

__global__ __launch_bounds__(256) void prep_gemm_kernel()
{
    extern __shared__ char smem[];
    const uint32_t sb = smem_u32(smem);
    const int tid = threadIdx.x;
    const int lane = tid & 31, wid = tid >> 5;
    const int wm = wid & 1, wn = wid >> 1;
    const int m0b = blockIdx.y * BM;     // n-dim of W
    const int n0b = blockIdx.x * BN;     // k-dim of W

    float c[4][4][4] = {};

    const int rowA = lane & 15;
    const int colA = (lane >> 4) * 8;
    const int rowB = (lane & 7) + ((lane >> 4) << 3);
    const int colB = ((lane >> 3) & 1) * 8;
    const uint32_t pA = (uint32_t)(wm * 64 + rowA) * PITCH + colA * 2;
    const uint32_t pB = (uint32_t)(wn * 32 + rowB) * PITCH + colB * 2;

    load_stage_p(sb, 0, m0b, n0b, 0, tid);
    CP_COMMIT();

    for (int kc = 0; kc < KCHUNKSP; kc++) {
        const int s = kc & 1;
        if (kc + 1 < KCHUNKSP) {
            load_stage_p(sb, s ^ 1, m0b, n0b, kc + 1, tid);
            CP_COMMIT();
            CP_WAIT(1);
        } else {
            CP_WAIT(0);
        }
        __syncthreads();

        const uint32_t st = sb + (uint32_t)s * STAGE_P;
        #pragma unroll
        for (int ks = 0; ks < 4; ks++) {
            uint32_t ah[4][4], al[4][4];
            #pragma unroll
            for (int mi = 0; mi < 4; mi++) {
                uint32_t adr = st + PA_HI + pA + mi * (16 * PITCH) + ks * 32;
                LDSM4(ah[mi], adr);
                LDSM4(al[mi], adr + (PA_LO - PA_HI));
            }
            uint32_t bh[4][2], bl[4][2];
            #pragma unroll
            for (int np = 0; np < 2; np++) {
                uint32_t adr = st + PB_HI + pB + np * (16 * PITCH) + ks * 32;
                uint32_t r[4];
                LDSM4(r, adr);
                bh[np * 2][0] = r[0]; bh[np * 2][1] = r[1];
                bh[np * 2 + 1][0] = r[2]; bh[np * 2 + 1][1] = r[3];
                LDSM4(r, adr + (PB_LO - PB_HI));
                bl[np * 2][0] = r[0]; bl[np * 2][1] = r[1];
                bl[np * 2 + 1][0] = r[2]; bl[np * 2 + 1][1] = r[3];
            }
            #pragma unroll
            for (int mi = 0; mi < 4; mi++)
                #pragma unroll
                for (int ni = 0; ni < 4; ni++) {
                    MMA16816(c[mi][ni], ah[mi], bh[ni]);
                    MMA16816(c[mi][ni], ah[mi], bl[ni]);
                    MMA16816(c[mi][ni], al[mi], bh[ni]);
                }
        }
        __syncthreads();
    }

    // epilogue: round W to fp16 (unscaled)
    const int mbase = m0b + wm * 64 + (lane >> 2);
    const int nbase = n0b + wn * 32 + (lane & 3) * 2;
    #pragma unroll
    for (int ni = 0; ni < 4; ni++) {
        const int n = nbase + ni * 8;
        #pragma unroll
        for (int mi = 0; mi < 4; mi++) {
            const int m = mbase + mi * 16;
            *reinterpret_cast<__half2*>(&g_Wh[(size_t)m * DIM + n]) =
                __floats2half2_rn(c[mi][ni][0], c[mi][ni][1]);
            *reinterpret_cast<__half2*>(&g_Wh[(size_t)(m + 8) * DIM + n]) =
                __floats2half2_rn(c[mi][ni][2], c[mi][ni][3]);
        }
    }
}

// ---------------------------------------------------------------------------
// Main GEMM: out[b][n] = 0.125 * sum_k X[b][k] * W[n][k] + b_out[n]
// ---------------------------------------------------------------------------
__device__ __forceinline__ void load_stage(uint32_t sb, int s, int m0b, int n0b,
                                           int kc, int tid)
{
    const uint32_t st = sb + (uint32_t)s * STAGE;
    const char* xh = reinterpret_cast<const char*>(g_Xh);
    const char* wh = reinterpret_cast<const char*>(g_Wh);
    const size_t kb = (size_t)kc * 128;

    #pragma unroll
    for (int j = 0; j < 4; j++) {
        int i = tid + j * 256;
        int r = i >> 3, c = i & 7;
        uint32_t so = (uint32_t)r * PITCH + c * 16;
        cp16(st + SA + so, xh + (size_t)(m0b + r) * 2048 + kb + c * 16);
        cp16(st + SB + so, wh + (size_t)(n0b + r) * 2048 + kb + c * 16);
    }
}

__global__ __launch_bounds__(256, 2) void gemm_mma_kernel(
    const float* __restrict__ b_out, float* __restrict__ out)
{
    extern __shared__ char smem[];
    const uint32_t sb = smem_u32(smem);
    const int tid = threadIdx.x;
    const int lane = tid & 31, wid = tid >> 5;
    const int wm = wid & 1, wn = wid >> 1;
    const int m0b = blockIdx.y * BM;
    const int n0b = blockIdx.x * BN;

    float c[4][4][4] = {};

    const int rowA = lane & 15;
    const int colA = (lane >> 4) * 8;
    const int rowB = (lane & 7) + ((lane >> 4) << 3);
    const int colB = ((lane >> 3) & 1) * 8;
    const uint32_t pA = (uint32_t)(wm * 64 + rowA) * PITCH + colA * 2;
    const uint32_t pB = (uint32_t)(wn * 32 + rowB) * PITCH + colB * 2;

    load_stage(sb, 0, m0b, n0b, 0, tid);
    CP_COMMIT();
    load_stage(sb, 1, m0b, n0b, 1, tid);
    CP_COMMIT();

    int sc = 0;
    for (int kc = 0; kc < KCHUNKS; kc++) {
        CP_WAIT(1);
        __syncthreads();   // all reads of chunk kc-1 done; its stage is free

        if (kc + 2 < KCHUNKS) {
            int sp = sc + 2; if (sp >= NSTAGE) sp -= NSTAGE;
            load_stage(sb, sp, m0b, n0b, kc + 2, tid);
        }
        CP_COMMIT();

        const uint32_t st = sb + (uint32_t)sc * STAGE;
        #pragma unroll
        for (int ks = 0; ks < 4; ks++) {
            uint32_t a[4][4];
            #pragma unroll
            for (int mi = 0; mi < 4; mi++)
                LDSM4(a[mi], st + SA + pA + mi * (16 * PITCH) + ks * 32);
            uint32_t b[4][2];
            #pragma unroll
            for (int np = 0; np < 2; np++) {
                uint32_t r[4];
                LDSM4(r, st + SB + pB + np * (16 * PITCH) + ks * 32);
                b[np * 2][0] = r[0]; b[np * 2][1] = r[1];
                b[np * 2 + 1][0] = r[2]; b[np * 2 + 1][1] = r[3];
            }
            #pragma unroll
            for (int mi = 0; mi < 4; mi++)
                #pragma unroll
                for (int ni = 0; ni < 4; ni++)
                    MMA16816(c[mi][ni], a[mi], b[ni]);
        }
        if (++sc >= NSTAGE) sc -= NSTAGE;
    }

    const int mbase = m0b + wm * 64 + (lane >> 2);
    const int nbase = n0b + wn * 32 + (lane & 3) * 2;
    #pragma unroll
    for (int ni = 0; ni < 4; ni++) {
        const int n = nbase + ni * 8;
        const float2 bias = *reinterpret_cast<const float2*>(&b_out[n]);
        #pragma unroll
        for (int mi = 0; mi < 4; mi++) {
            const int m = mbase + mi * 16;
            float2 v0 = { fmaf(0.125f, c[mi][ni][0], bias.x),
                          fmaf(0.125f, c[mi][ni][1], bias.y) };
            float2 v1 = { fmaf(0.125f, c[mi][ni][2], bias.x),
                          fmaf(0.125f, c[mi][ni][3], bias.y) };
            *reinterpret_cast<float2*>(&out[(size_t)m * DIM + n]) = v0;
            *reinterpret_cast<float2*>(&out[(size_t)(m + 8) * DIM + n]) = v1;
        }
    }
}

// ---------------------------------------------------------------------------
// Row L2-normalize: out = y * (32/max(||y||,eps)) * g
// ---------------------------------------------------------------------------
__global__ __launch_bounds__(256) void rmsnorm_kernel(
    const float* __restrict__ g, float* __restrict__ y)
{
    const int warp = (blockIdx.x * blockDim.x + threadIdx.x) >> 5;
    const int lane = threadIdx.x & 31;
    if (warp >= BATCH) return;
    float* __restrict__ row = y + (size_t)warp * DIM;

    float4 vals[8];
    float ss = 0.f;
    #pragma unroll
    for (int i = 0; i < 8; i++) {
        vals[i] = *reinterpret_cast<const float4*>(&row[lane * 4 + i * 128]);
        ss += vals[i].x * vals[i].x + vals[i].y * vals[i].y +
              vals[i].z * vals[i].z + vals[i].w * vals[i].w;
    }
    #pragma unroll
    for (int o = 16; o > 0; o >>= 1) ss += __shfl_xor_sync(0xFFFFFFFFu, ss, o);
    const float inv = 32.0f / fmaxf(sqrtf(ss), 1e-12f);
    #pragma unroll
    for (int i = 0; i < 8; i++) {
        int n = lane * 4 + i * 128;
        float4 gv = *reinterpret_cast<const float4*>(&g[n]);
        float4 o;
        o.x = vals[i].x * inv * gv.x;
        o.y = vals[i].y * inv * gv.y;
        o.z = vals[i].z * inv * gv.z;
        o.w = vals[i].w * inv * gv.w;
        *reinterpret_cast<float4*>(&row[n]) = o;
    }
}

// ---------------------------------------------------------------------------
extern "C" void kernel_launch(void* const* d_in, const int* in_sizes, int n_in,
                              void* d_out, int out_size)
{
    const float* x     = (const float*)d_in[0];
    const float* w_qkv = (const float*)d_in[1];
    const float* w_out = (const float*)d_in[2];
    const float* b_out = (const float*)d_in[3];
    const float* g     = (const float*)d_in[4];
    float* out = (float*)d_out;

    cudaFuncSetAttribute(gemm_mma_kernel,
                         cudaFuncAttributeMaxDynamicSharedMemorySize, GEMM_SMEM);
    cudaFuncSetAttribute(prep_gemm_kernel,
                         cudaFuncAttributeMaxDynamicSharedMemorySize, PREP_SMEM);

    conv_kernel<<<2688, 256>>>((const float4*)x, w_qkv, w_out);
    prep_gemm_kernel<<<dim3(DIM / BN, DIM / BM), 256, PREP_SMEM>>>();
    gemm_mma_kernel<<<dim3(DIM / BN, BATCH / BM), 256, GEMM_SMEM>>>(b_out, out);
    rmsnorm_kernel<<<(BATCH * 32) / 256, 256>>>(g, out);
}